// round 17
// baseline (speedup 1.0000x reference)
#include <cuda_runtime.h>
#include <cuda_bf16.h>
#include <cuda_fp16.h>
#include <math.h>
#include <stdint.h>

#define BATCH 4096
#define HID 128
#define NSTEP 16

// ---------------- global data ------------------------------------------------
__device__ __align__(16) __nv_bfloat16 d_W_hi[512 * 192];   // reordered cols: n' = j*4+gate
__device__ __align__(16) __nv_bfloat16 d_W_lo[512 * 192];
__device__ __align__(16) float d_bias[512];                  // reordered
__device__ __align__(16) __half d_img_h[(size_t)BATCH * 2 * 4096];  // fp16 images (67MB)

// ---------------- smem layout (bytes), 16-sample CTA --------------------------
// x:  [16][72] bf16, stride 144: hi @0 (2304), lo @2304
// h:  ping-pong bufs @4608: buf k @ 4608+k*8704 (hi 4352, lo +4352); [16][136] bf16
// region R @22016 (83968 B):
//   phase G: img 4 pairs x 2 bufs x 8192 @22016; filt 4 pairs x 4608 @87552
//   phase M: B 8 warps x 2 bufs x 4608 @22016 (73728 B)
// c lives in REGISTERS (static thread->(row,j) map across steps)
#define SX_HI   0
#define SX_LO   2304
#define SH0     4608
#define HBUF    8704
#define SIMG    22016
#define SB2     22016
#define SFILT   87552
#define SM_TOTAL 105984

// ---------------- helpers ----------------------------------------------------
__device__ __forceinline__ uint32_t smem_u32(const void* p) {
    uint32_t a;
    asm("{ .reg .u64 t; cvta.to.shared.u64 t, %1; cvt.u32.u64 %0, t; }" : "=r"(a) : "l"(p));
    return a;
}
__device__ __forceinline__ void cp_async16(uint32_t dst, const void* src) {
    asm volatile("cp.async.cg.shared.global [%0], [%1], 16;" :: "r"(dst), "l"(src) : "memory");
}
__device__ __forceinline__ void cp_commit() {
    asm volatile("cp.async.commit_group;" ::: "memory");
}
template <int N>
__device__ __forceinline__ void cp_wait() {
    asm volatile("cp.async.wait_group %0;" :: "n"(N) : "memory");
}
__device__ __forceinline__ void bar_pair(int id) {
    asm volatile("bar.sync %0, 64;" :: "r"(id) : "memory");
}
__device__ __forceinline__ void ldm_x4(uint32_t* r, uint32_t a) {
    asm volatile("ldmatrix.sync.aligned.m8n8.x4.shared.b16 {%0,%1,%2,%3}, [%4];"
                 : "=r"(r[0]), "=r"(r[1]), "=r"(r[2]), "=r"(r[3]) : "r"(a));
}
__device__ __forceinline__ void ldm_x4_t(uint32_t* r, uint32_t a) {
    asm volatile("ldmatrix.sync.aligned.m8n8.x4.trans.shared.b16 {%0,%1,%2,%3}, [%4];"
                 : "=r"(r[0]), "=r"(r[1]), "=r"(r[2]), "=r"(r[3]) : "r"(a));
}
__device__ __forceinline__ void ldm_x2(uint32_t* r, uint32_t a) {
    asm volatile("ldmatrix.sync.aligned.m8n8.x2.shared.b16 {%0,%1}, [%2];"
                 : "=r"(r[0]), "=r"(r[1]) : "r"(a));
}
__device__ __forceinline__ void mma_bf16(float* d, const uint32_t* a, const uint32_t* b) {
    asm volatile(
        "mma.sync.aligned.m16n8k16.row.col.f32.bf16.bf16.f32 "
        "{%0,%1,%2,%3}, {%4,%5,%6,%7}, {%8,%9}, {%0,%1,%2,%3};"
        : "+f"(d[0]), "+f"(d[1]), "+f"(d[2]), "+f"(d[3])
        : "r"(a[0]), "r"(a[1]), "r"(a[2]), "r"(a[3]), "r"(b[0]), "r"(b[1]));
}
__device__ __forceinline__ void mma_f16(float* d, const uint32_t* a, const uint32_t* b) {
    asm volatile(
        "mma.sync.aligned.m16n8k16.row.col.f32.f16.f16.f32 "
        "{%0,%1,%2,%3}, {%4,%5,%6,%7}, {%8,%9}, {%0,%1,%2,%3};"
        : "+f"(d[0]), "+f"(d[1]), "+f"(d[2]), "+f"(d[3])
        : "r"(a[0]), "r"(a[1]), "r"(a[2]), "r"(a[3]), "r"(b[0]), "r"(b[1]));
}
__device__ __forceinline__ uint32_t pack_h2(float x, float y) {
    __half2 h = __floats2half2_rn(x, y);
    return *reinterpret_cast<uint32_t*>(&h);
}

// ---------------- prologue ---------------------------------------------------
__global__ void prologue_kernel(const float* __restrict__ imgs,
                                const float* __restrict__ W_ih,
                                const float* __restrict__ W_hh,
                                const float* __restrict__ b_ih,
                                const float* __restrict__ b_hh) {
    int bid = blockIdx.x, tid = threadIdx.x;
    if (bid < 8192) {
        const float4* in4 = reinterpret_cast<const float4*>(imgs);
        uint2* out2 = reinterpret_cast<uint2*>(d_img_h);
        for (int i = bid * 256 + tid; i < 8388608; i += 8192 * 256) {
            float4 v = in4[i];
            __half2 a = __floats2half2_rn(v.x, v.y);
            __half2 c = __floats2half2_rn(v.z, v.w);
            uint2 o;
            o.x = *reinterpret_cast<uint32_t*>(&a);
            o.y = *reinterpret_cast<uint32_t*>(&c);
            out2[i] = o;
        }
    } else {
        int idx = (bid - 8192) * 256 + tid;  // exactly 512*192
        int np = idx / 192, k = idx % 192;
        int gate = np & 3, j = np >> 2;
        int orig = gate * 128 + j;
        float w = (k < 64) ? W_ih[orig * 64 + k] : W_hh[orig * 128 + (k - 64)];
        __nv_bfloat16 hi = __float2bfloat16(w);
        __nv_bfloat16 lo = __float2bfloat16(w - __bfloat162float(hi));
        d_W_hi[np * 192 + k] = hi;
        d_W_lo[np * 192 + k] = lo;
        if (k == 0) d_bias[np] = b_ih[orig] + b_hh[orig];
    }
}

// ---------------- persistent mega kernel (256 threads, 2 CTAs/SM) ------------
__global__ __launch_bounds__(256, 2) void arc_kernel(
    float* __restrict__ out,
    const float* __restrict__ W_g, const float* __restrict__ b_g)
{
    extern __shared__ char sm[];
    uint32_t sb = smem_u32(sm);
    int tid = threadIdx.x, wid = tid >> 5, lane = tid & 31;
    int pair = wid >> 1, wh = wid & 1;      // pairs 0..3
    int bar_id = 1 + pair;
    int bm0 = blockIdx.x * 16;

    __nv_bfloat16* s_xhi = reinterpret_cast<__nv_bfloat16*>(sm + SX_HI);
    __nv_bfloat16* s_xlo = reinterpret_cast<__nv_bfloat16*>(sm + SX_LO);

    const int tva[3] = {0, 0, 1};
    const int tvb[3] = {0, 1, 0};

    // c in registers: c_reg[sub][nt][hh] on even lanes (static map across steps)
    float c_reg[2][4][2];
#pragma unroll
    for (int s2 = 0; s2 < 2; s2++)
#pragma unroll
        for (int nt = 0; nt < 4; nt++)
#pragma unroll
            for (int hh = 0; hh < 2; hh++) c_reg[s2][nt][hh] = 0.0f;

    // zero x + both h buffers (22016 bytes)
    for (int i = tid; i < 22016 / 4; i += 256)
        reinterpret_cast<float*>(sm)[i] = 0.0f;

#define ISSUE_IMG(pbuf, smp, selv) do {                                          \
        const __half* src_ = d_img_h + ((size_t)(smp) * 2 + (size_t)(selv)) * 4096; \
        uint32_t dst_ = sb + SIMG + (pair * 2 + (pbuf)) * 8192;                  \
        _Pragma("unroll")                                                        \
        for (int j_ = 0; j_ < 8; j_++) {                                         \
            int cc_ = wh * 256 + lane + j_ * 32;                                 \
            int rr_ = cc_ >> 3, ch_ = cc_ & 7;                                   \
            cp_async16(dst_ + rr_ * 128 + ((ch_ ^ (rr_ & 7)) * 16),              \
                       src_ + rr_ * 64 + ch_ * 8);                               \
        }                                                                        \
        cp_commit();                                                             \
    } while (0)

    __syncthreads();

    for (int t = 0; t < NSTEP; t++) {
        int sel = t & 1;
        uint32_t h_rd = (uint32_t)(SH0 + (t & 1) * HBUF);
        uint32_t h_wr = (uint32_t)(SH0 + ((t + 1) & 1) * HBUF);
        __nv_bfloat16* s_hhi_w = reinterpret_cast<__nv_bfloat16*>(sm + h_wr);
        __nv_bfloat16* s_hlo_w = reinterpret_cast<__nv_bfloat16*>(sm + h_wr + 4352);

        // ===== phase G: pair handles 4 samples (4 rounds) ====================
        uint32_t filtb = sb + SFILT + pair * 4608;
        ISSUE_IMG(0, bm0 + pair * 4, sel);
        for (int r = 0; r < 4; r++) {
            int s_loc = pair * 4 + r;
            int pbuf = r & 1;
            if (r < 3) ISSUE_IMG(pbuf ^ 1, bm0 + s_loc + 1, sel);

            // gp pieces: gpa = gp[wh], gp2 = gp[2]
            float h4[4];
            {
                uint2 rhu = *reinterpret_cast<uint2*>(sm + h_rd + s_loc * 272 + lane * 8);
                uint2 rlu = *reinterpret_cast<uint2*>(sm + h_rd + 4352 + s_loc * 272 + lane * 8);
                __nv_bfloat162* hh = reinterpret_cast<__nv_bfloat162*>(&rhu);
                __nv_bfloat162* ll = reinterpret_cast<__nv_bfloat162*>(&rlu);
                float2 h01 = __bfloat1622float2(hh[0]);
                float2 h23 = __bfloat1622float2(hh[1]);
                float2 l01 = __bfloat1622float2(ll[0]);
                float2 l23 = __bfloat1622float2(ll[1]);
                h4[0] = h01.x + l01.x; h4[1] = h01.y + l01.y;
                h4[2] = h23.x + l23.x; h4[3] = h23.y + l23.y;
            }
            float gpa, gp2;
            {
                float pa, p2;
                {
                    float4 wv = __ldg(reinterpret_cast<const float4*>(&W_g[wh * 128 + lane * 4]));
                    pa = h4[0] * wv.x + h4[1] * wv.y + h4[2] * wv.z + h4[3] * wv.w;
                }
                {
                    float4 wv = __ldg(reinterpret_cast<const float4*>(&W_g[2 * 128 + lane * 4]));
                    p2 = h4[0] * wv.x + h4[1] * wv.y + h4[2] * wv.z + h4[3] * wv.w;
                }
#pragma unroll
                for (int o = 16; o > 0; o >>= 1) {
                    pa += __shfl_xor_sync(0xffffffffu, pa, o);
                    p2 += __shfl_xor_sync(0xffffffffu, p2, o);
                }
                gpa = tanhf(pa + __ldg(&b_g[wh]));
                gp2 = tanhf(p2 + __ldg(&b_g[2]));
            }

            // own filter bank (warp0: Fh, warp1: Fw), normalized, fp16 hi/lo
            {
                float ad  = fabsf(gp2);
                float dlt = 8.0f * (1.0f - ad);
                float gam = expf(1.0f - 2.0f * ad);
                float ig  = 1.0f / gam;
                float cpre = 1.0f / (3.14159265358979323f * gam);
                float fi0 = (float)(2 * lane), fi1 = fi0 + 1.0f;
                float center = 31.5f * (gpa + 1.0f);
                uint32_t base = filtb + (wh ? 2304u : 0u);
#pragma unroll
                for (int tt = 0; tt < 8; tt++) {
                    float gpix = center + dlt * ((float)tt - 3.5f);
                    float u0 = (fi0 - gpix) * ig, u1 = (fi1 - gpix) * ig;
                    float v0 = __fdividef(cpre, 1.0f + u0 * u0);
                    float v1 = __fdividef(cpre, 1.0f + u1 * u1);
                    float s = v0 + v1;
#pragma unroll
                    for (int o = 16; o > 0; o >>= 1) s += __shfl_xor_sync(0xffffffffu, s, o);
                    float inv = __fdividef(1.0f, s + 1e-4f);
                    v0 *= inv; v1 *= inv;
                    uint32_t hi2 = pack_h2(v0, v1);
                    __half2 hh2 = *reinterpret_cast<__half2*>(&hi2);
                    float2 hf = __half22float2(hh2);
                    uint32_t lo2 = pack_h2(v0 - hf.x, v1 - hf.y);
                    uint32_t dst = base + tt * 144 + lane * 4;
                    asm volatile("st.shared.b32 [%0], %1;" :: "r"(dst), "r"(hi2));
                    asm volatile("st.shared.b32 [%0], %1;" :: "r"(dst + 1152), "r"(lo2));
                }
            }
            if (r < 3) cp_wait<1>(); else cp_wait<0>();
            bar_pair(bar_id);

            // G1: warp handles image-column half
            float accL[4][4];
#pragma unroll
            for (int nt = 0; nt < 4; nt++)
#pragma unroll
                for (int q = 0; q < 4; q++) accL[nt][q] = 0.0f;

            uint32_t fh = filtb + (lane & 15) * 144 + (lane >> 4) * 16;
            uint32_t ibuf = sb + SIMG + (pair * 2 + pbuf) * 8192 + (lane & 15) * 128;
            int cb = lane >> 4, xorv = lane & 7;

#pragma unroll
            for (int kk = 0; kk < 4; kk++) {
                uint32_t ah[4];
                ldm_x4(ah, fh + kk * 32);
#pragma unroll
                for (int ntl = 0; ntl < 2; ntl++) {
                    int nt2 = 2 * wh + ntl;
                    uint32_t bb[4];
                    uint32_t ch = (uint32_t)(((2 * nt2 + cb) ^ xorv) * 16);
                    ldm_x4_t(bb, ibuf + kk * 2048 + ch);
                    mma_f16(accL[2 * ntl],     ah, bb);
                    mma_f16(accL[2 * ntl + 1], ah, bb + 2);
                }
            }
            float psL[4][2];
#pragma unroll
            for (int nt = 0; nt < 4; nt++) {
                psL[nt][0] = accL[nt][0] + accL[nt][2];
                psL[nt][1] = accL[nt][1] + accL[nt][3];
            }

            // G2: warp handles K-chunks kk2 = 2wh + {0,1}
            float acc2[4] = {0.0f, 0.0f, 0.0f, 0.0f};
            uint32_t fwb = filtb + 2304 + (lane & 7) * 144 + ((lane >> 3) & 1) * 16;
#pragma unroll
            for (int kl = 0; kl < 2; kl++) {
                int kk2 = 2 * wh + kl;
                float p0 = psL[2 * kl][0],     p1 = psL[2 * kl][1];
                float q0 = psL[2 * kl + 1][0], q1 = psL[2 * kl + 1][1];
                uint32_t ah[4], al[4];
                ah[0] = pack_h2(p0, p1);
                ah[2] = pack_h2(q0, q1);
                ah[1] = 0u; ah[3] = 0u;
                {
                    __half2 h0 = *reinterpret_cast<__half2*>(&ah[0]);
                    __half2 h2 = *reinterpret_cast<__half2*>(&ah[2]);
                    float2 f0 = __half22float2(h0);
                    float2 f2 = __half22float2(h2);
                    al[0] = pack_h2(p0 - f0.x, p1 - f0.y);
                    al[2] = pack_h2(q0 - f2.x, q1 - f2.y);
                    al[1] = 0u; al[3] = 0u;
                }
                uint32_t bh[2], bl[2];
                ldm_x2(bh, fwb + kk2 * 32);
                ldm_x2(bl, fwb + 1152 + kk2 * 32);
                mma_f16(acc2, ah, bh);
                mma_f16(acc2, al, bh);
                mma_f16(acc2, ah, bl);
            }

            bar_pair(bar_id);
            if (wh == 1) {
                asm volatile("st.shared.v2.f32 [%0], {%1, %2};"
                             :: "r"(filtb + lane * 8), "f"(acc2[0]), "f"(acc2[1]) : "memory");
            }
            bar_pair(bar_id);
            if (wh == 0) {
                float o0, o1;
                asm volatile("ld.shared.v2.f32 {%0, %1}, [%2];"
                             : "=f"(o0), "=f"(o1) : "r"(filtb + lane * 8));
                float v0 = acc2[0] + o0, v1 = acc2[1] + o1;
                int c8 = (lane >> 2) * 8 + (lane & 3) * 2;
                __nv_bfloat16 h0 = __float2bfloat16(v0);
                __nv_bfloat16 h1 = __float2bfloat16(v1);
                s_xhi[s_loc * 72 + c8]     = h0;
                s_xhi[s_loc * 72 + c8 + 1] = h1;
                s_xlo[s_loc * 72 + c8]     = __float2bfloat16(v0 - __bfloat162float(h0));
                s_xlo[s_loc * 72 + c8 + 1] = __float2bfloat16(v1 - __bfloat162float(h1));
            }
        }
        __syncthreads();   // x complete; img+filt dead -> B overlays

        // ===== phase M: warp owns cols [wid*64, +64) via 2 sub-passes ========
#define LOAD_BW(c9v, bufv, subv) do {                                            \
        int t2_ = (c9v) / 3, kb2_ = (c9v) % 3;                                   \
        const __nv_bfloat16* ws_ = tvb[t2_] ? d_W_lo : d_W_hi;                   \
        _Pragma("unroll")                                                        \
        for (int p_ = 0; p_ < 8; p_++) {                                         \
            int ix_ = lane + p_ * 32;                                            \
            int rw_ = ix_ >> 3, cc_ = ix_ & 7;                                   \
            cp_async16(sb + SB2 + (wid * 2 + (bufv)) * 4608 + rw_ * 144 + cc_ * 16, \
                       ws_ + (wid * 64 + (subv) * 32 + rw_) * 192 + kb2_ * 64 + cc_ * 8); \
        }                                                                        \
        cp_commit();                                                             \
    } while (0)

#pragma unroll
        for (int sub = 0; sub < 2; sub++) {
            float mac[4][4];
#pragma unroll
            for (int nt = 0; nt < 4; nt++)
#pragma unroll
                for (int q = 0; q < 4; q++) mac[nt][q] = 0.0f;

            LOAD_BW(0, 0, sub);
            for (int c9 = 0; c9 < 9; c9++) {
                int buf = c9 & 1;
                if (c9 < 8) LOAD_BW(c9 + 1, buf ^ 1, sub);
                if (c9 < 8) cp_wait<1>(); else cp_wait<0>();
                __syncwarp();

                int t_ = c9 / 3, kb = c9 % 3;
                uint32_t abase;
                if (kb == 0)
                    abase = sb + (tva[t_] ? SX_LO : SX_HI)
                          + (lane & 15) * 144 + (lane >> 4) * 16;
                else
                    abase = sb + h_rd + (tva[t_] ? 4352u : 0u)
                          + (lane & 15) * 272 + (lane >> 4) * 16 + (kb - 1) * 128;
                uint32_t bbase = sb + SB2 + (wid * 2 + buf) * 4608
                               + (lane & 7) * 144 + ((lane >> 3) & 1) * 16;

#pragma unroll
                for (int ks = 0; ks < 4; ks++) {
                    uint32_t a[4], bfr[4][2];
                    ldm_x4(a, abase + ks * 32);
#pragma unroll
                    for (int nt = 0; nt < 4; nt++)
                        ldm_x2(bfr[nt], bbase + nt * (8 * 144) + ks * 32);
#pragma unroll
                    for (int nt = 0; nt < 4; nt++)
                        mma_bf16(mac[nt], a, bfr[nt]);
                }
            }

            // LSTM epilogue (warp-exclusive j range; c in registers)
#pragma unroll
            for (int nt = 0; nt < 4; nt++) {
                int col = wid * 64 + sub * 32 + nt * 8 + (lane & 3) * 2;
                float b0 = __ldg(&d_bias[col]);
                float b1 = __ldg(&d_bias[col + 1]);
                float a0 = mac[nt][0] + b0, a1 = mac[nt][1] + b1;
                float a2 = mac[nt][2] + b0, a3 = mac[nt][3] + b1;
                float p0 = __shfl_xor_sync(0xffffffffu, a0, 1);
                float p1 = __shfl_xor_sync(0xffffffffu, a1, 1);
                float p2 = __shfl_xor_sync(0xffffffffu, a2, 1);
                float p3 = __shfl_xor_sync(0xffffffffu, a3, 1);
                if (!(lane & 1)) {
                    int j = (col >> 2);
                    int row = lane >> 2;
#pragma unroll
                    for (int hh = 0; hh < 2; hh++) {
                        int rr = row + hh * 8;
                        float gi = hh ? a2 : a0;
                        float gf = hh ? a3 : a1;
                        float gg = hh ? p2 : p0;
                        float go = hh ? p3 : p1;
                        float co = c_reg[sub][nt][hh];
                        float si = 1.0f / (1.0f + expf(-gi));
                        float sf = 1.0f / (1.0f + expf(-gf));
                        float so = 1.0f / (1.0f + expf(-go));
                        float cn = sf * co + si * tanhf(gg);
                        float hn = so * tanhf(cn);
                        c_reg[sub][nt][hh] = cn;
                        __nv_bfloat16 hhi = __float2bfloat16(hn);
                        s_hhi_w[rr * 136 + j] = hhi;
                        s_hlo_w[rr * 136 + j] = __float2bfloat16(hn - __bfloat162float(hhi));
                        if (t == NSTEP - 1)
                            out[(bm0 + rr) * 128 + j] = hn;
                    }
                }
            }
        }
#undef LOAD_BW
        __syncthreads();   // h_{t+1} complete; B dead -> img reuses
    }
#undef ISSUE_IMG
}

// ---------------- launch ----------------------------------------------------
extern "C" void kernel_launch(void* const* d_in, const int* in_sizes, int n_in,
                              void* d_out, int out_size)
{
    const float* imgs = (const float*)d_in[0];
    const float* W_ih = (const float*)d_in[1];
    const float* W_hh = (const float*)d_in[2];
    const float* b_ih = (const float*)d_in[3];
    const float* b_hh = (const float*)d_in[4];
    const float* W_g  = (const float*)d_in[5];
    const float* b_g  = (const float*)d_in[6];
    float* out = (float*)d_out;

    static int smem_set = 0;
    if (!smem_set) {
        cudaFuncSetAttribute(arc_kernel,
                             cudaFuncAttributeMaxDynamicSharedMemorySize, SM_TOTAL);
        smem_set = 1;
    }

    prologue_kernel<<<8576, 256>>>(imgs, W_ih, W_hh, b_ih, b_hh);
    arc_kernel<<<BATCH / 16, 256, SM_TOTAL>>>(out, W_g, b_g);
}